// round 2
// baseline (speedup 1.0000x reference)
#include <cuda_runtime.h>

#define DD 512
#define KK 16

// ---- device scratch (no allocations allowed) ----
__device__ float g_c2[KK];
__device__ float g_bsum[4096];

// ---- packed f32x2 helpers (Blackwell FFMA2) ----
__device__ __forceinline__ unsigned long long pk2(float lo, float hi) {
    unsigned long long r;
    asm("mov.b64 %0, {%1,%2};" : "=l"(r) : "f"(lo), "f"(hi));
    return r;
}
__device__ __forceinline__ void upk2(unsigned long long v, float& lo, float& hi) {
    asm("mov.b64 {%0,%1}, %2;" : "=f"(lo), "=f"(hi) : "l"(v));
}
__device__ __forceinline__ unsigned long long ffma2(unsigned long long a,
                                                    unsigned long long b,
                                                    unsigned long long c) {
    unsigned long long d;
    asm("fma.rn.f32x2 %0, %1, %2, %3;" : "=l"(d) : "l"(a), "l"(b), "l"(c));
    return d;
}

// ---- kernel 0: codebook squared norms ----
__global__ void vq_prep(const float* __restrict__ cb) {
    int k = threadIdx.x >> 5, lane = threadIdx.x & 31;
    float s = 0.f;
    for (int j = lane; j < DD; j += 32) {
        float v = cb[k * DD + j];
        s = fmaf(v, v, s);
    }
    #pragma unroll
    for (int o = 16; o; o >>= 1) s += __shfl_xor_sync(0xffffffffu, s, o);
    if (lane == 0) g_c2[k] = s;
}

// ---- kernel 1: main VQ — one row per thread ----
__global__ void __launch_bounds__(128) vq_main(
    const float* __restrict__ z, const float* __restrict__ cb,
    float* __restrict__ zq, float* __restrict__ idx_out,
    int has_idx, int nrows)
{
    __shared__ float sc[KK * DD];     // 32 KB codebook
    __shared__ float sred[128];

    // cooperative codebook stage (coalesced float4)
    for (int i = threadIdx.x; i < KK * DD / 4; i += blockDim.x)
        ((float4*)sc)[i] = ((const float4*)cb)[i];
    __syncthreads();

    int r = blockIdx.x * blockDim.x + threadIdx.x;
    float rloss = 0.f;

    if (r < nrows) {
        const float4* zr = (const float4*)(z + (size_t)r * DD);

        // 4-way split accumulation per codebook entry: acc[k][0] takes (x,y)
        // pairs, acc[k][1] takes (z,w) pairs; each f32x2 lane is its own
        // sequential chain of 128 adds -> dot error ~5e-6 << fp32 ulp at 512.
        unsigned long long acc0[KK], acc1[KK];
        #pragma unroll
        for (int k = 0; k < KK; k++) { acc0[k] = 0ull; acc1[k] = 0ull; }
        unsigned long long z2a = 0ull, z2b = 0ull;

        #pragma unroll 4
        for (int i = 0; i < DD / 4; i++) {
            float4 zv = zr[i];
            unsigned long long a = pk2(zv.x, zv.y);
            unsigned long long b = pk2(zv.z, zv.w);
            z2a = ffma2(a, a, z2a);
            z2b = ffma2(b, b, z2b);
            #pragma unroll
            for (int k = 0; k < KK; k++) {
                // LDS.128, same address across all lanes -> broadcast, conflict-free
                float4 cv = *(const float4*)(sc + k * DD + i * 4);
                acc0[k] = ffma2(a, pk2(cv.x, cv.y), acc0[k]);
                acc1[k] = ffma2(b, pk2(cv.z, cv.w), acc1[k]);
            }
        }

        float l0, h0, l1, h1;
        upk2(z2a, l0, h0); upk2(z2b, l1, h1);
        float z2 = (l0 + h0) + (l1 + h1);          // |z|^2  (~512)

        // Reference-matching quantization: dist = fl(fl(z2 - 2*dot) + c2).
        // At magnitude ~512 (ulp 6.1e-5) near-ties collapse to exact fp32
        // ties for both us and the reference; first-index rule then matches
        // jnp.argmin deterministically.
        float best = 3.4e38f; int bi = 0;
        #pragma unroll
        for (int k = 0; k < KK; k++) {
            upk2(acc0[k], l0, h0); upk2(acc1[k], l1, h1);
            float dot = (l0 + h0) + (l1 + h1);
            float t = z2 - 2.0f * dot;              // fl(z2 - 2*dot)
            float dist = t + g_c2[k];               // fl(t + c2)
            if (dist < best) { best = dist; bi = k; }
        }
        rloss = best;                                // |z - c_best|^2 (quantized)

        // gather z_q row from global codebook (L1-resident, avoids SMEM bank conflicts)
        const float4* crow = (const float4*)(cb + bi * DD);
        float4* orow = (float4*)(zq + (size_t)r * DD);
        #pragma unroll 4
        for (int i = 0; i < DD / 4; i++) orow[i] = crow[i];

        if (has_idx) idx_out[r] = (float)bi;
    }

    // deterministic per-block loss partial (no atomics)
    sred[threadIdx.x] = rloss;
    __syncthreads();
    #pragma unroll
    for (int s2 = 64; s2 > 0; s2 >>= 1) {
        if (threadIdx.x < s2) sred[threadIdx.x] += sred[threadIdx.x + s2];
        __syncthreads();
    }
    if (threadIdx.x == 0) g_bsum[blockIdx.x] = sred[0];
}

// ---- kernel 2: finalize loss ----
__global__ void vq_final(float* __restrict__ loss_out, int nb, float scale) {
    __shared__ float sred[512];
    float s = 0.f;
    for (int i = threadIdx.x; i < nb; i += blockDim.x) s += g_bsum[i];
    sred[threadIdx.x] = s;
    __syncthreads();
    for (int st = 256; st > 0; st >>= 1) {
        if (threadIdx.x < st) sred[threadIdx.x] += sred[threadIdx.x + st];
        __syncthreads();
    }
    if (threadIdx.x == 0) loss_out[0] = sred[0] * scale;
}

extern "C" void kernel_launch(void* const* d_in, const int* in_sizes, int n_in,
                              void* d_out, int out_size) {
    const float* z  = (const float*)d_in[0];
    const float* cb = (const float*)d_in[1];
    int zn = in_sizes[0];          // N * D
    int N  = zn / DD;              // rows

    float* zq = (float*)d_out;
    int has_idx = (out_size >= zn + N) ? 1 : 0;
    float* idxp = has_idx ? ((float*)d_out + zn) : (float*)d_out;

    vq_prep<<<1, KK * 32>>>(cb);

    int nb = (N + 127) / 128;
    vq_main<<<nb, 128>>>(z, cb, zq, idxp, has_idx, N);

    if (out_size >= zn + N + 1) {
        float scale = 1.25f / ((float)N * (float)DD);
        vq_final<<<1, 512>>>((float*)d_out + zn + N, nb, scale);
    }
}

// round 3
// speedup vs baseline: 1.4614x; 1.4614x over previous
#include <cuda_runtime.h>

#define DD  512
#define KK  16
#define RPB 128            // rows per block (== blockDim.x)
#define CH  16             // dims per staged chunk
#define NCH (DD/CH)        // 32 chunks
#define F4C (CH/4)         // 4 float4 per row per chunk

// ---- device scratch (no allocations allowed) ----
__device__ float g_bsum[4096];
__device__ unsigned int g_done = 0;

// ---- packed f32x2 helpers (Blackwell FFMA2) ----
__device__ __forceinline__ unsigned long long pk2(float lo, float hi) {
    unsigned long long r;
    asm("mov.b64 %0, {%1,%2};" : "=l"(r) : "f"(lo), "f"(hi));
    return r;
}
__device__ __forceinline__ void upk2(unsigned long long v, float& lo, float& hi) {
    asm("mov.b64 {%0,%1}, %2;" : "=f"(lo), "=f"(hi) : "l"(v));
}
__device__ __forceinline__ unsigned long long ffma2(unsigned long long a,
                                                    unsigned long long b,
                                                    unsigned long long c) {
    unsigned long long d;
    asm("fma.rn.f32x2 %0, %1, %2, %3;" : "=l"(d) : "l"(a), "l"(b), "l"(c));
    return d;
}

__global__ void __launch_bounds__(RPB) vq_fused(
    const float* __restrict__ z, const float* __restrict__ cb,
    float* __restrict__ zq, float* __restrict__ idxp, float* __restrict__ lossp,
    int nrows, int nblocks, float scale)
{
    __shared__ float  sc[KK * DD];       // 32 KB codebook
    __shared__ float4 zs[F4C * RPB];     // 8 KB z staging (swizzled)
    __shared__ float  c2s[KK];
    __shared__ float  sred[RPB];
    __shared__ int    bis[RPB];
    __shared__ unsigned int ticket;

    const int t = threadIdx.x;
    const int w = t >> 5, lane = t & 31;

    // ---- stage codebook (coalesced float4) ----
    for (int i = t; i < KK * DD / 4; i += RPB)
        ((float4*)sc)[i] = ((const float4*)cb)[i];
    __syncthreads();

    // ---- codebook squared norms (same arithmetic order as the passing vq_prep) ----
    #pragma unroll
    for (int kk = 0; kk < 4; kk++) {
        int k = w * 4 + kk;
        float s = 0.f;
        for (int j = lane; j < DD; j += 32) {
            float v = sc[k * DD + j];
            s = fmaf(v, v, s);
        }
        #pragma unroll
        for (int o = 16; o; o >>= 1) s += __shfl_xor_sync(0xffffffffu, s, o);
        if (lane == 0) c2s[k] = s;
    }
    // c2s consumed after the main loop; the loop's __syncthreads covers it.

    const size_t rowbase = (size_t)blockIdx.x * RPB;
    const int r = (int)rowbase + t;
    const bool active = r < nrows;

    // ---- prefetch chunk 0: thread handles (row = t/4 + 32i, j = t%4) ----
    const int jj = t & 3;
    const int rl = t >> 2;                 // 0..31
    const float4* zg = (const float4*)z;
    float4 g[4];
    #pragma unroll
    for (int i = 0; i < 4; i++) {
        int rr = rl + 32 * i;
        size_t gi = (rowbase + rr) * (DD / 4) + jj;   // chunk 0
        g[i] = ((int)(rowbase + rr) < nrows) ? zg[gi] : make_float4(0.f, 0.f, 0.f, 0.f);
    }

    // ---- split accumulators (identical structure to passing kernel) ----
    unsigned long long acc0[KK], acc1[KK];
    #pragma unroll
    for (int k = 0; k < KK; k++) { acc0[k] = 0ull; acc1[k] = 0ull; }
    unsigned long long z2a = 0ull, z2b = 0ull;

    for (int c = 0; c < NCH; c++) {
        __syncthreads();                   // staging buffer free
        #pragma unroll
        for (int i = 0; i < 4; i++) {
            int rr = rl + 32 * i;
            zs[jj * RPB + (rr ^ jj)] = g[i];   // swizzled STS
        }
        if (c + 1 < NCH) {
            #pragma unroll
            for (int i = 0; i < 4; i++) {     // prefetch next chunk (overlaps compute)
                int rr = rl + 32 * i;
                size_t gi = (rowbase + rr) * (DD / 4) + (size_t)(c + 1) * F4C + jj;
                g[i] = ((int)(rowbase + rr) < nrows) ? zg[gi]
                                                     : make_float4(0.f, 0.f, 0.f, 0.f);
            }
        }
        __syncthreads();

        // ---- compute: this thread's row = t; float4 order = c*4 + j (sequential, as before)
        #pragma unroll
        for (int j = 0; j < F4C; j++) {
            float4 zv = zs[j * RPB + (t ^ j)];
            unsigned long long a = pk2(zv.x, zv.y);
            unsigned long long b = pk2(zv.z, zv.w);
            z2a = ffma2(a, a, z2a);
            z2b = ffma2(b, b, z2b);
            const float* cbase = sc + c * CH + j * 4;
            #pragma unroll
            for (int k = 0; k < KK; k++) {
                // broadcast LDS.128 (same address across lanes)
                float4 cv = *(const float4*)(cbase + k * DD);
                acc0[k] = ffma2(a, pk2(cv.x, cv.y), acc0[k]);
                acc1[k] = ffma2(b, pk2(cv.z, cv.w), acc1[k]);
            }
        }
    }

    // ---- argmin with reference-matching quantization: fl(fl(z2 - 2*dot) + c2) ----
    float l0, h0, l1, h1;
    upk2(z2a, l0, h0); upk2(z2b, l1, h1);
    float z2 = (l0 + h0) + (l1 + h1);

    float best = 3.4e38f; int bi = 0;
    #pragma unroll
    for (int k = 0; k < KK; k++) {
        upk2(acc0[k], l0, h0); upk2(acc1[k], l1, h1);
        float dot = (l0 + h0) + (l1 + h1);
        float dist = (z2 - 2.0f * dot) + c2s[k];
        if (dist < best) { best = dist; bi = k; }
    }
    float rloss = active ? best : 0.f;
    bis[t] = bi;
    if (active && idxp) idxp[r] = (float)bi;

    // ---- cooperative coalesced z_q write: one full row per iteration ----
    __syncthreads();
    float4* zqg = (float4*)zq;
    const int rmax = min(RPB, nrows - (int)rowbase);
    for (int rr = 0; rr < rmax; rr++) {
        int b = bis[rr];                                    // broadcast
        float4 cv = *(const float4*)(sc + b * DD + t * 4);  // lane-consecutive LDS.128
        zqg[(rowbase + rr) * (DD / 4) + t] = cv;            // coalesced STG.128
    }

    // ---- deterministic block loss partial ----
    sred[t] = rloss;
    __syncthreads();
    #pragma unroll
    for (int s2 = 64; s2 > 0; s2 >>= 1) {
        if (t < s2) sred[t] += sred[t + s2];
        __syncthreads();
    }
    if (t == 0) g_bsum[blockIdx.x] = sred[0];

    // ---- last-block finalize (deterministic order; counter reset for graph replay) ----
    if (t == 0) {
        __threadfence();
        ticket = atomicAdd(&g_done, 1u);
    }
    __syncthreads();
    if (ticket == (unsigned)(nblocks - 1)) {
        float s = 0.f;
        for (int i = t; i < nblocks; i += RPB) s += __ldcg(&g_bsum[i]);
        sred[t] = s;
        __syncthreads();
        #pragma unroll
        for (int s2 = 64; s2 > 0; s2 >>= 1) {
            if (t < s2) sred[t] += sred[t + s2];
            __syncthreads();
        }
        if (t == 0) {
            if (lossp) lossp[0] = sred[0] * scale;
            g_done = 0;
        }
    }
}

extern "C" void kernel_launch(void* const* d_in, const int* in_sizes, int n_in,
                              void* d_out, int out_size) {
    const float* z  = (const float*)d_in[0];
    const float* cb = (const float*)d_in[1];
    int zn = in_sizes[0];          // N * D
    int N  = zn / DD;

    float* zq = (float*)d_out;
    int has_idx  = (out_size >= zn + N) ? 1 : 0;
    float* idxp  = has_idx ? ((float*)d_out + zn) : nullptr;
    float* lossp = (out_size >= zn + N + 1) ? ((float*)d_out + zn + N) : nullptr;

    int nb = (N + RPB - 1) / RPB;
    float scale = 1.25f / ((float)N * (float)DD);

    vq_fused<<<nb, RPB>>>(z, cb, zq, idxp, lossp, N, nb, scale);
}

// round 4
// speedup vs baseline: 1.5196x; 1.0398x over previous
#include <cuda_runtime.h>

#define DD  512
#define KK  16
#define RPB 128            // rows per block (== blockDim.x)
#define CH  16             // dims per staged chunk
#define NCH (DD/CH)        // 32 chunks
#define F4C (CH/4)         // 4 float4 per row per chunk

// ---- device scratch (no allocations allowed) ----
__device__ float g_bsum[4096];
__device__ unsigned int g_done = 0;

// ---- packed f32x2 helpers (Blackwell FFMA2) ----
__device__ __forceinline__ void upk2(unsigned long long v, float& lo, float& hi) {
    asm("mov.b64 {%0,%1}, %2;" : "=f"(lo), "=f"(hi) : "l"(v));
}
__device__ __forceinline__ unsigned long long ffma2(unsigned long long a,
                                                    unsigned long long b,
                                                    unsigned long long c) {
    unsigned long long d;
    asm("fma.rn.f32x2 %0, %1, %2, %3;" : "=l"(d) : "l"(a), "l"(b), "l"(c));
    return d;
}

__global__ void __launch_bounds__(RPB, 4) vq_fused(
    const float* __restrict__ z, const float* __restrict__ cb,
    float* __restrict__ zq, float* __restrict__ idxp, float* __restrict__ lossp,
    int nrows, int nblocks, float scale)
{
    __shared__ float      sc[KK * DD];          // 32 KB codebook
    __shared__ ulonglong2 zs[2][F4C * RPB];     // 2 x 8 KB z staging (double buffer)
    __shared__ float      c2s[KK];
    __shared__ float      sred[RPB];
    __shared__ int        bis[RPB];
    __shared__ unsigned int ticket;

    const int t = threadIdx.x;
    const int w = t >> 5, lane = t & 31;

    const size_t rowbase = (size_t)blockIdx.x * RPB;
    const int r = (int)rowbase + t;
    const bool active = r < nrows;

    // ---- stage codebook (coalesced float4) ----
    for (int i = t; i < KK * DD / 4; i += RPB)
        ((float4*)sc)[i] = ((const float4*)cb)[i];

    // ---- prefetch z chunk 0: thread handles (row = t/4 + 32i, j = t%4) ----
    // ulonglong2 has identical bits to float4: .x = packed(x,y), .y = packed(z,w)
    const int jj = t & 3;
    const int rl = t >> 2;                 // 0..31
    const ulonglong2* zg = (const ulonglong2*)z;
    ulonglong2 g[4];
    #pragma unroll
    for (int i = 0; i < 4; i++) {
        int rr = rl + 32 * i;
        size_t gi = (rowbase + rr) * (DD / 4) + jj;   // chunk 0
        if ((int)(rowbase + rr) < nrows) g[i] = zg[gi];
        else { g[i].x = 0ull; g[i].y = 0ull; }
    }

    __syncthreads();                       // sc visible

    // ---- codebook squared norms (same arithmetic order as passing kernel) ----
    #pragma unroll
    for (int kk = 0; kk < 4; kk++) {
        int k = w * 4 + kk;
        float s = 0.f;
        for (int j = lane; j < DD; j += 32) {
            float v = sc[k * DD + j];
            s = fmaf(v, v, s);
        }
        #pragma unroll
        for (int o = 16; o; o >>= 1) s += __shfl_xor_sync(0xffffffffu, s, o);
        if (lane == 0) c2s[k] = s;
    }

    // ---- stage chunk 0 into buffer 0 (swizzled) ----
    #pragma unroll
    for (int i = 0; i < 4; i++) {
        int rr = rl + 32 * i;
        zs[0][jj * RPB + (rr ^ jj)] = g[i];
    }

    // ---- split accumulators (identical structure/order to passing kernel) ----
    unsigned long long acc0[KK], acc1[KK];
    #pragma unroll
    for (int k = 0; k < KK; k++) { acc0[k] = 0ull; acc1[k] = 0ull; }
    unsigned long long z2a = 0ull, z2b = 0ull;

    for (int c = 0; c < NCH; c++) {
        // prefetch chunk c+1 (latency overlaps barrier + compute)
        if (c + 1 < NCH) {
            #pragma unroll
            for (int i = 0; i < 4; i++) {
                int rr = rl + 32 * i;
                size_t gi = (rowbase + rr) * (DD / 4) + (size_t)(c + 1) * F4C + jj;
                if ((int)(rowbase + rr) < nrows) g[i] = zg[gi];
                else { g[i].x = 0ull; g[i].y = 0ull; }
            }
        }
        __syncthreads();                   // buf[c&1] visible; buf[(c+1)&1] free

        const ulonglong2* zbuf = zs[c & 1];
        #pragma unroll
        for (int j = 0; j < F4C; j++) {
            ulonglong2 zv = zbuf[j * RPB + (t ^ j)];   // .x=(x,y) .y=(z,w)
            z2a = ffma2(zv.x, zv.x, z2a);
            z2b = ffma2(zv.y, zv.y, z2b);
            const float* cbase = sc + c * CH + j * 4;
            #pragma unroll
            for (int k = 0; k < KK; k++) {
                // broadcast LDS.128 (same address across lanes), read as b64 pair
                ulonglong2 cv = *(const ulonglong2*)(cbase + k * DD);
                acc0[k] = ffma2(zv.x, cv.x, acc0[k]);
                acc1[k] = ffma2(zv.y, cv.y, acc1[k]);
            }
        }

        if (c + 1 < NCH) {
            #pragma unroll
            for (int i = 0; i < 4; i++) {
                int rr = rl + 32 * i;
                zs[(c + 1) & 1][jj * RPB + (rr ^ jj)] = g[i];
            }
        }
    }

    // ---- argmin with reference-matching quantization: fl(fl(z2 - 2*dot) + c2) ----
    float l0, h0, l1, h1;
    upk2(z2a, l0, h0); upk2(z2b, l1, h1);
    float z2 = (l0 + h0) + (l1 + h1);

    float best = 3.4e38f; int bi = 0;
    #pragma unroll
    for (int k = 0; k < KK; k++) {
        upk2(acc0[k], l0, h0); upk2(acc1[k], l1, h1);
        float dot = (l0 + h0) + (l1 + h1);
        float dist = (z2 - 2.0f * dot) + c2s[k];
        if (dist < best) { best = dist; bi = k; }
    }
    float rloss = active ? best : 0.f;
    bis[t] = bi;
    if (active && idxp) idxp[r] = (float)bi;

    // ---- cooperative coalesced z_q write: one full row per iteration ----
    __syncthreads();
    float4* zqg = (float4*)zq;
    const int rmax = min(RPB, nrows - (int)rowbase);
    for (int rr = 0; rr < rmax; rr++) {
        int b = bis[rr];                                    // broadcast
        float4 cv = *(const float4*)(sc + b * DD + t * 4);  // lane-consecutive LDS.128
        zqg[(rowbase + rr) * (DD / 4) + t] = cv;            // coalesced STG.128
    }

    // ---- deterministic block loss partial ----
    sred[t] = rloss;
    __syncthreads();
    #pragma unroll
    for (int s2 = 64; s2 > 0; s2 >>= 1) {
        if (t < s2) sred[t] += sred[t + s2];
        __syncthreads();
    }
    if (t == 0) g_bsum[blockIdx.x] = sred[0];

    // ---- last-block finalize (deterministic order; counter reset for graph replay) ----
    if (t == 0) {
        __threadfence();
        ticket = atomicAdd(&g_done, 1u);
    }
    __syncthreads();
    if (ticket == (unsigned)(nblocks - 1)) {
        float s = 0.f;
        for (int i = t; i < nblocks; i += RPB) s += __ldcg(&g_bsum[i]);
        sred[t] = s;
        __syncthreads();
        #pragma unroll
        for (int s2 = 64; s2 > 0; s2 >>= 1) {
            if (t < s2) sred[t] += sred[t + s2];
            __syncthreads();
        }
        if (t == 0) {
            if (lossp) lossp[0] = sred[0] * scale;
            g_done = 0;
        }
    }
}

extern "C" void kernel_launch(void* const* d_in, const int* in_sizes, int n_in,
                              void* d_out, int out_size) {
    const float* z  = (const float*)d_in[0];
    const float* cb = (const float*)d_in[1];
    int zn = in_sizes[0];          // N * D
    int N  = zn / DD;

    float* zq = (float*)d_out;
    int has_idx  = (out_size >= zn + N) ? 1 : 0;
    float* idxp  = has_idx ? ((float*)d_out + zn) : nullptr;
    float* lossp = (out_size >= zn + N + 1) ? ((float*)d_out + zn + N) : nullptr;

    int nb = (N + RPB - 1) / RPB;
    float scale = 1.25f / ((float)N * (float)DD);

    vq_fused<<<nb, RPB>>>(z, cb, zq, idxp, lossp, N, nb, scale);
}

// round 5
// speedup vs baseline: 1.6527x; 1.0876x over previous
#include <cuda_runtime.h>

#define DD  512
#define KK  16
#define RPB 128            // rows per block (== blockDim.x)
#define CH  16             // dims per staged chunk
#define NCH (DD/CH)        // 32 chunks
#define F4C (CH/4)         // 4 float4 per row per chunk

// ---- device scratch (no allocations allowed) ----
__device__ float g_bsum[4096];
__device__ unsigned int g_done = 0;

// ---- packed f32x2 helpers (Blackwell FFMA2) ----
__device__ __forceinline__ void upk2(unsigned long long v, float& lo, float& hi) {
    asm("mov.b64 {%0,%1}, %2;" : "=f"(lo), "=f"(hi) : "l"(v));
}
__device__ __forceinline__ unsigned long long ffma2(unsigned long long a,
                                                    unsigned long long b,
                                                    unsigned long long c) {
    unsigned long long d;
    asm("fma.rn.f32x2 %0, %1, %2, %3;" : "=l"(d) : "l"(a), "l"(b), "l"(c));
    return d;
}
// guaranteed 128-bit shared load
__device__ __forceinline__ void lds128(unsigned long long& a, unsigned long long& b,
                                       unsigned addr) {
    asm volatile("ld.shared.v2.u64 {%0,%1}, [%2];" : "=l"(a), "=l"(b) : "r"(addr));
}
__device__ __forceinline__ void cpasync16(unsigned dst, const void* src) {
    asm volatile("cp.async.cg.shared.global [%0], [%1], 16;" :: "r"(dst), "l"(src) : "memory");
}

__global__ void __launch_bounds__(RPB, 4) vq_fused(
    const float* __restrict__ z, const float* __restrict__ cb,
    float* __restrict__ zq, float* __restrict__ idxp, float* __restrict__ lossp,
    int nrows, int nblocks, float scale)
{
    __shared__ float      sc[KK * DD];          // 32 KB codebook
    __shared__ ulonglong2 zs[2][F4C * RPB];     // 2 x 8 KB z staging (double buffer)
    __shared__ float      c2s[KK];
    __shared__ float      sdist[2][RPB];        // per-half best dist (reused as loss partials)
    __shared__ int        sidx[2][RPB];         // per-half best idx  ([0] reused as final idx)
    __shared__ unsigned int ticket;

    const int t = threadIdx.x;
    const int w = t >> 5, lane = t & 31;
    const int half  = w & 1;                    // k-half this warp owns
    const int khalf = half * 8;
    const int r0    = (w >> 1) * 64 + lane;     // this lane's rows: r0, r0+32 (block-local)
    const size_t rowbase = (size_t)blockIdx.x * RPB;

    const unsigned sc_sa = (unsigned)__cvta_generic_to_shared(sc);
    const unsigned zs_sa = (unsigned)__cvta_generic_to_shared(zs);

    const int jj = t & 3;                       // staging role: float4-slot
    const int rl = t >> 2;                      // staging role: row lane
    const long lastrow = (long)nrows - 1;

    // ---- cp.async chunk 0 ----
    #pragma unroll
    for (int i = 0; i < 4; i++) {
        int rr = rl + 32 * i;
        long gr = (long)(rowbase + rr); if (gr > lastrow) gr = lastrow;
        const char* src = (const char*)z + ((size_t)gr * (DD / 4) + jj) * 16;
        unsigned dst = zs_sa + (unsigned)((jj * RPB + (rr ^ jj)) * 16);
        cpasync16(dst, src);
    }
    asm volatile("cp.async.commit_group;" ::: "memory");

    // ---- stage codebook (coalesced float4) ----
    for (int i = t; i < KK * DD / 4; i += RPB)
        ((float4*)sc)[i] = ((const float4*)cb)[i];
    __syncthreads();

    // ---- codebook squared norms (identical arithmetic to passing kernel) ----
    #pragma unroll
    for (int kk = 0; kk < 4; kk++) {
        int k = w * 4 + kk;
        float s = 0.f;
        for (int j = lane; j < DD; j += 32) {
            float v = sc[k * DD + j];
            s = fmaf(v, v, s);
        }
        #pragma unroll
        for (int o = 16; o; o >>= 1) s += __shfl_xor_sync(0xffffffffu, s, o);
        if (lane == 0) c2s[k] = s;
    }

    // ---- split accumulators: [k-in-half], rg0 = row r0, rg1 = row r0+32 ----
    unsigned long long a00[8], a10[8], a01[8], a11[8];
    #pragma unroll
    for (int k = 0; k < 8; k++) { a00[k] = 0ull; a10[k] = 0ull; a01[k] = 0ull; a11[k] = 0ull; }
    unsigned long long z2a0 = 0ull, z2b0 = 0ull, z2a1 = 0ull, z2b1 = 0ull;

    for (int c = 0; c < NCH; c++) {
        asm volatile("cp.async.wait_group 0;" ::: "memory");
        __syncthreads();                 // chunk c visible to all; chunk c-1 readers done

        if (c + 1 < NCH) {               // prefetch next chunk into the other buffer
            #pragma unroll
            for (int i = 0; i < 4; i++) {
                int rr = rl + 32 * i;
                long gr = (long)(rowbase + rr); if (gr > lastrow) gr = lastrow;
                const char* src = (const char*)z +
                    ((size_t)gr * (DD / 4) + (size_t)(c + 1) * F4C + jj) * 16;
                unsigned dst = zs_sa +
                    (unsigned)((((c + 1) & 1) * F4C * RPB + jj * RPB + (rr ^ jj)) * 16);
                cpasync16(dst, src);
            }
            asm volatile("cp.async.commit_group;" ::: "memory");
        }

        const unsigned bufb = zs_sa + (unsigned)((c & 1) * (F4C * RPB * 16));
        const unsigned cbb  = sc_sa + (unsigned)((khalf * DD + c * CH) * 4);

        #pragma unroll
        for (int j = 0; j < F4C; j++) {
            unsigned long long za, zb, ya, yb;
            lds128(za, zb, bufb + (unsigned)((j * RPB + (r0 ^ j)) * 16));
            lds128(ya, yb, bufb + (unsigned)((j * RPB + ((r0 + 32) ^ j)) * 16));
            z2a0 = ffma2(za, za, z2a0);  z2b0 = ffma2(zb, zb, z2b0);
            z2a1 = ffma2(ya, ya, z2a1);  z2b1 = ffma2(yb, yb, z2b1);
            #pragma unroll
            for (int k = 0; k < 8; k++) {
                unsigned long long ca, cbv;   // cb[khalf+k][c*CH+j*4 .. +3], one LDS.128 for 2 rows
                lds128(ca, cbv, cbb + (unsigned)((k * DD + j * 4) * 4));
                a00[k] = ffma2(za, ca,  a00[k]);
                a10[k] = ffma2(zb, cbv, a10[k]);
                a01[k] = ffma2(ya, ca,  a01[k]);
                a11[k] = ffma2(yb, cbv, a11[k]);
            }
        }
    }

    // ---- per-half argmin with reference-matching quantization ----
    {
        float l0, h0, l1, h1;
        upk2(z2a0, l0, h0); upk2(z2b0, l1, h1);
        float z2 = (l0 + h0) + (l1 + h1);
        float best = 3.4e38f; int bi = 0;
        #pragma unroll
        for (int k = 0; k < 8; k++) {
            upk2(a00[k], l0, h0); upk2(a10[k], l1, h1);
            float dot = (l0 + h0) + (l1 + h1);
            float dist = (z2 - 2.0f * dot) + c2s[khalf + k];
            if (dist < best) { best = dist; bi = khalf + k; }
        }
        sdist[half][r0] = best; sidx[half][r0] = bi;
    }
    {
        float l0, h0, l1, h1;
        upk2(z2a1, l0, h0); upk2(z2b1, l1, h1);
        float z2 = (l0 + h0) + (l1 + h1);
        float best = 3.4e38f; int bi = 0;
        #pragma unroll
        for (int k = 0; k < 8; k++) {
            upk2(a01[k], l0, h0); upk2(a11[k], l1, h1);
            float dot = (l0 + h0) + (l1 + h1);
            float dist = (z2 - 2.0f * dot) + c2s[khalf + k];
            if (dist < best) { best = dist; bi = khalf + k; }
        }
        sdist[half][r0 + 32] = best; sidx[half][r0 + 32] = bi;
    }
    __syncthreads();

    // ---- combine halves (half0 wins ties == sequential first-min over k=0..15) ----
    const int r = (int)rowbase + t;
    const bool active = r < nrows;
    {
        float d0 = sdist[0][t], d1 = sdist[1][t];
        int   bfin  = (d1 < d0) ? sidx[1][t] : sidx[0][t];
        float rloss = (d1 < d0) ? d1 : d0;
        if (!active) rloss = 0.f;
        if (active && idxp) idxp[r] = (float)bfin;
        sidx[0][t]  = bfin;      // per-thread overwrite of own slot (safe)
        sdist[0][t] = rloss;     // reuse as loss partial
    }
    __syncthreads();

    // ---- cooperative coalesced z_q write: one full row per iteration ----
    float4* zqg = (float4*)zq;
    const int rmax = min(RPB, nrows - (int)rowbase);
    for (int rr = 0; rr < rmax; rr++) {
        int b = sidx[0][rr];                                // broadcast
        float4 cv = *(const float4*)(sc + b * DD + t * 4);  // lane-consecutive LDS.128
        zqg[(rowbase + rr) * (DD / 4) + t] = cv;            // coalesced STG.128
    }

    // ---- deterministic block loss partial (tree over sdist[0]) ----
    #pragma unroll
    for (int s2 = 64; s2 > 0; s2 >>= 1) {
        if (t < s2) sdist[0][t] += sdist[0][t + s2];
        __syncthreads();
    }
    if (t == 0) g_bsum[blockIdx.x] = sdist[0][0];

    // ---- last-block finalize (deterministic order; counter reset for graph replay) ----
    if (t == 0) {
        __threadfence();
        ticket = atomicAdd(&g_done, 1u);
    }
    __syncthreads();
    if (ticket == (unsigned)(nblocks - 1)) {
        float s = 0.f;
        for (int i = t; i < nblocks; i += RPB) s += __ldcg(&g_bsum[i]);
        sdist[1][t] = s;
        __syncthreads();
        #pragma unroll
        for (int s2 = 64; s2 > 0; s2 >>= 1) {
            if (t < s2) sdist[1][t] += sdist[1][t + s2];
            __syncthreads();
        }
        if (t == 0) {
            if (lossp) lossp[0] = sdist[1][0] * scale;
            g_done = 0;
        }
    }
}

extern "C" void kernel_launch(void* const* d_in, const int* in_sizes, int n_in,
                              void* d_out, int out_size) {
    const float* z  = (const float*)d_in[0];
    const float* cb = (const float*)d_in[1];
    int zn = in_sizes[0];          // N * D
    int N  = zn / DD;

    float* zq = (float*)d_out;
    int has_idx  = (out_size >= zn + N) ? 1 : 0;
    float* idxp  = has_idx ? ((float*)d_out + zn) : nullptr;
    float* lossp = (out_size >= zn + N + 1) ? ((float*)d_out + zn + N) : nullptr;

    int nb = (N + RPB - 1) / RPB;
    float scale = 1.25f / ((float)N * (float)DD);

    vq_fused<<<nb, RPB>>>(z, cb, zq, idxp, lossp, N, nb, scale);
}

// round 6
// speedup vs baseline: 1.6840x; 1.0190x over previous
#include <cuda_runtime.h>

#define DD  512
#define KK  16
#define RPB 128            // rows per block (== blockDim.x)
#define CH  16             // dims per staged chunk
#define NCH (DD/CH)        // 32 chunks
#define F4C (CH/4)         // 4 float4 per row per chunk

// ---- device scratch (no allocations allowed) ----
__device__ float g_bsum[4096];
__device__ unsigned int g_done = 0;

// ---- packed f32x2 helpers (Blackwell FFMA2) ----
__device__ __forceinline__ void upk2(unsigned long long v, float& lo, float& hi) {
    asm("mov.b64 {%0,%1}, %2;" : "=f"(lo), "=f"(hi) : "l"(v));
}
__device__ __forceinline__ unsigned long long ffma2(unsigned long long a,
                                                    unsigned long long b,
                                                    unsigned long long c) {
    unsigned long long d;
    asm("fma.rn.f32x2 %0, %1, %2, %3;" : "=l"(d) : "l"(a), "l"(b), "l"(c));
    return d;
}
__device__ __forceinline__ void cpasync16(unsigned dst, const void* src) {
    asm volatile("cp.async.cg.shared.global [%0], [%1], 16;" :: "r"(dst), "l"(src) : "memory");
}

__global__ void __launch_bounds__(RPB, 4) vq_fused(
    const float* __restrict__ z, const float* __restrict__ cb,
    float* __restrict__ zq, float* __restrict__ idxp, float* __restrict__ lossp,
    int nrows, int nblocks, float scale)
{
    __shared__ float      sc[KK * DD];          // 32 KB codebook
    __shared__ ulonglong2 zs[2][F4C * RPB];     // 2 x 8 KB z staging (double buffer)
    __shared__ float      c2s[KK];
    __shared__ float      sdist[2][RPB];        // per-half best dist (reused as loss partials)
    __shared__ int        sidx[2][RPB];         // per-half best idx  ([0] reused as final idx)
    __shared__ unsigned int ticket;

    const int t = threadIdx.x;
    const int w = t >> 5, lane = t & 31;
    const int half  = w & 1;                    // k-half this warp owns
    const int khalf = half * 8;
    const int r0    = (w >> 1) * 64 + lane;     // this lane's rows: r0, r0+32 (block-local)
    const size_t rowbase = (size_t)blockIdx.x * RPB;

    const unsigned zs_sa = (unsigned)__cvta_generic_to_shared(zs);

    const int jj = t & 3;                       // staging role: float4-slot
    const int rl = t >> 2;                      // staging role: row lane
    const long lastrow = (long)nrows - 1;

    // ---- cp.async chunk 0 ----
    #pragma unroll
    for (int i = 0; i < 4; i++) {
        int rr = rl + 32 * i;
        long gr = (long)(rowbase + rr); if (gr > lastrow) gr = lastrow;
        const char* src = (const char*)z + ((size_t)gr * (DD / 4) + jj) * 16;
        unsigned dst = zs_sa + (unsigned)((jj * RPB + (rr ^ jj)) * 16);
        cpasync16(dst, src);
    }
    asm volatile("cp.async.commit_group;" ::: "memory");

    // ---- stage codebook (coalesced float4) ----
    for (int i = t; i < KK * DD / 4; i += RPB)
        ((float4*)sc)[i] = ((const float4*)cb)[i];
    __syncthreads();

    // ---- codebook squared norms (identical arithmetic to passing kernel) ----
    #pragma unroll
    for (int kk = 0; kk < 4; kk++) {
        int k = w * 4 + kk;
        float s = 0.f;
        for (int j = lane; j < DD; j += 32) {
            float v = sc[k * DD + j];
            s = fmaf(v, v, s);
        }
        #pragma unroll
        for (int o = 16; o; o >>= 1) s += __shfl_xor_sync(0xffffffffu, s, o);
        if (lane == 0) c2s[k] = s;
    }

    // ---- split accumulators: [k-in-half], rg0 = row r0, rg1 = row r0+32 ----
    unsigned long long a00[8], a10[8], a01[8], a11[8];
    #pragma unroll
    for (int k = 0; k < 8; k++) { a00[k] = 0ull; a10[k] = 0ull; a01[k] = 0ull; a11[k] = 0ull; }
    unsigned long long z2a0 = 0ull, z2b0 = 0ull, z2a1 = 0ull, z2b1 = 0ull;

    for (int c = 0; c < NCH; c++) {
        asm volatile("cp.async.wait_group 0;" ::: "memory");
        __syncthreads();                 // chunk c visible to all; chunk c-1 readers done

        if (c + 1 < NCH) {               // prefetch next chunk into the other buffer
            #pragma unroll
            for (int i = 0; i < 4; i++) {
                int rr = rl + 32 * i;
                long gr = (long)(rowbase + rr); if (gr > lastrow) gr = lastrow;
                const char* src = (const char*)z +
                    ((size_t)gr * (DD / 4) + (size_t)(c + 1) * F4C + jj) * 16;
                unsigned dst = zs_sa +
                    (unsigned)((((c + 1) & 1) * F4C * RPB + jj * RPB + (rr ^ jj)) * 16);
                cpasync16(dst, src);
            }
            asm volatile("cp.async.commit_group;" ::: "memory");
        }

        // C++ shared loads: compiler-visible LDS.128, free to hoist/pipeline
        const ulonglong2* zbuf = zs[c & 1];
        const float* cbb = sc + (khalf * DD + c * CH);

        #pragma unroll
        for (int j = 0; j < F4C; j++) {
            ulonglong2 zv0 = zbuf[j * RPB + (r0 ^ j)];          // row r0:    .x=(x,y) .y=(z,w)
            ulonglong2 zv1 = zbuf[j * RPB + ((r0 + 32) ^ j)];   // row r0+32
            z2a0 = ffma2(zv0.x, zv0.x, z2a0);  z2b0 = ffma2(zv0.y, zv0.y, z2b0);
            z2a1 = ffma2(zv1.x, zv1.x, z2a1);  z2b1 = ffma2(zv1.y, zv1.y, z2b1);
            #pragma unroll
            for (int k = 0; k < 8; k++) {
                // broadcast LDS.128 (same address across lanes), one load feeds 2 rows
                ulonglong2 cv = *(const ulonglong2*)(cbb + k * DD + j * 4);
                a00[k] = ffma2(zv0.x, cv.x, a00[k]);
                a10[k] = ffma2(zv0.y, cv.y, a10[k]);
                a01[k] = ffma2(zv1.x, cv.x, a01[k]);
                a11[k] = ffma2(zv1.y, cv.y, a11[k]);
            }
        }
    }

    // ---- per-half argmin with reference-matching quantization ----
    {
        float l0, h0, l1, h1;
        upk2(z2a0, l0, h0); upk2(z2b0, l1, h1);
        float z2 = (l0 + h0) + (l1 + h1);
        float best = 3.4e38f; int bi = 0;
        #pragma unroll
        for (int k = 0; k < 8; k++) {
            upk2(a00[k], l0, h0); upk2(a10[k], l1, h1);
            float dot = (l0 + h0) + (l1 + h1);
            float dist = (z2 - 2.0f * dot) + c2s[khalf + k];
            if (dist < best) { best = dist; bi = khalf + k; }
        }
        sdist[half][r0] = best; sidx[half][r0] = bi;
    }
    {
        float l0, h0, l1, h1;
        upk2(z2a1, l0, h0); upk2(z2b1, l1, h1);
        float z2 = (l0 + h0) + (l1 + h1);
        float best = 3.4e38f; int bi = 0;
        #pragma unroll
        for (int k = 0; k < 8; k++) {
            upk2(a01[k], l0, h0); upk2(a11[k], l1, h1);
            float dot = (l0 + h0) + (l1 + h1);
            float dist = (z2 - 2.0f * dot) + c2s[khalf + k];
            if (dist < best) { best = dist; bi = khalf + k; }
        }
        sdist[half][r0 + 32] = best; sidx[half][r0 + 32] = bi;
    }
    __syncthreads();

    // ---- combine halves (half0 wins ties == sequential first-min over k=0..15) ----
    const int r = (int)rowbase + t;
    const bool active = r < nrows;
    {
        float d0 = sdist[0][t], d1 = sdist[1][t];
        int   bfin  = (d1 < d0) ? sidx[1][t] : sidx[0][t];
        float rloss = (d1 < d0) ? d1 : d0;
        if (!active) rloss = 0.f;
        if (active && idxp) idxp[r] = (float)bfin;
        sidx[0][t]  = bfin;      // per-thread overwrite of own slot (safe)
        sdist[0][t] = rloss;     // reuse as loss partial
    }
    __syncthreads();

    // ---- cooperative coalesced z_q write: one full row per iteration ----
    float4* zqg = (float4*)zq;
    const int rmax = min(RPB, nrows - (int)rowbase);
    for (int rr = 0; rr < rmax; rr++) {
        int b = sidx[0][rr];                                // broadcast
        float4 cv = *(const float4*)(sc + b * DD + t * 4);  // lane-consecutive LDS.128
        zqg[(rowbase + rr) * (DD / 4) + t] = cv;            // coalesced STG.128
    }

    // ---- deterministic block loss partial (tree over sdist[0]) ----
    #pragma unroll
    for (int s2 = 64; s2 > 0; s2 >>= 1) {
        if (t < s2) sdist[0][t] += sdist[0][t + s2];
        __syncthreads();
    }
    if (t == 0) g_bsum[blockIdx.x] = sdist[0][0];

    // ---- last-block finalize (deterministic order; counter reset for graph replay) ----
    if (t == 0) {
        __threadfence();
        ticket = atomicAdd(&g_done, 1u);
    }
    __syncthreads();
    if (ticket == (unsigned)(nblocks - 1)) {
        float s = 0.f;
        for (int i = t; i < nblocks; i += RPB) s += __ldcg(&g_bsum[i]);
        sdist[1][t] = s;
        __syncthreads();
        #pragma unroll
        for (int s2 = 64; s2 > 0; s2 >>= 1) {
            if (t < s2) sdist[1][t] += sdist[1][t + s2];
            __syncthreads();
        }
        if (t == 0) {
            if (lossp) lossp[0] = sdist[1][0] * scale;
            g_done = 0;
        }
    }
}

extern "C" void kernel_launch(void* const* d_in, const int* in_sizes, int n_in,
                              void* d_out, int out_size) {
    const float* z  = (const float*)d_in[0];
    const float* cb = (const float*)d_in[1];
    int zn = in_sizes[0];          // N * D
    int N  = zn / DD;

    float* zq = (float*)d_out;
    int has_idx  = (out_size >= zn + N) ? 1 : 0;
    float* idxp  = has_idx ? ((float*)d_out + zn) : nullptr;
    float* lossp = (out_size >= zn + N + 1) ? ((float*)d_out + zn + N) : nullptr;

    int nb = (N + RPB - 1) / RPB;
    float scale = 1.25f / ((float)N * (float)DD);

    vq_fused<<<nb, RPB>>>(z, cb, zq, idxp, lossp, N, nb, scale);
}